// round 14
// baseline (speedup 1.0000x reference)
#include <cuda_runtime.h>

// z_hat [B,T,D] f32, P [B,T] f32, lengths [B] i32 -> out [B,T,D] f32
#define BB 4
#define TT 4096
#define DD 512
#define CC 256              // chunks along T  (best-known config)
#define LL 16               // chunk length
#define D4 128              // float4 lanes per row (DD/4)
#define NCHUNK (BB*CC)      // 1024 chunks, f = b*CC + c
#define NSCAN 512           // scan instances = BB * D4

// Scratch (__device__ globals; allocation-free rule). idx f = b*CC + c.
__device__ float g_Bsum[NCHUNK * DD];
__device__ float g_A[NCHUNK];
__device__ float g_Zinit[NCHUNK * DD];
__device__ unsigned g_ctr;   // monotonic; each launch adds exactly NCHUNK
                             // (wrap-safe: 2^32 % 1024 == 0) -> deterministic

// ---------------------------------------------------------------------------
// kA = K1 (per-chunk weighted reduction) + embedded K2 (cross-chunk scan).
// After a block publishes its summary it takes a ticket. The last NSCAN
// ticket-holders (still resident; ALL 1024 blocks fit on-chip concurrently
// at 8 blocks/SM, so the spin cannot deadlock) wait for every ticket, then
// each runs one (b, d4-lane) scan instance over the CC chunk maps.
// ---------------------------------------------------------------------------
__global__ void __launch_bounds__(128, 8) kA_summary_scan(
    const float* __restrict__ z, const float* __restrict__ P,
    const int* __restrict__ lengths)
{
    const int b = blockIdx.x;     // fastest -> masked/active mixed across SMs
    const int c = blockIdx.y;
    const int lane = threadIdx.x; // float4 lane over D
    const int len = lengths[b];
    const int t0 = c * LL;

    // ---------------- Phase A: chunk summary (skip if masked) ----------------
    if (t0 < len) {
        float pcl[LL];
#pragma unroll
        for (int k = 0; k < LL; ++k) {
            float p = __ldg(&P[b * TT + t0 + k]);     // warp-uniform broadcast
            pcl[k] = fminf(fmaxf(p, 0.0f), 1.0f - 1e-6f);
        }
        float w[LL];
        float r = 1.0f;
#pragma unroll
        for (int k = LL - 1; k >= 0; --k) {
            w[k] = fmaxf(pcl[k], 1e-6f) * r;   // w[k]=pe[k]*prod_{m>k}q[m]
            r *= (1.0f - pcl[k]);
        }

        const float4* __restrict__ zp =
            (const float4*)(z + ((size_t)b * TT + t0) * DD);
        float4 a0 = make_float4(0.f, 0.f, 0.f, 0.f);
        float4 a1 = make_float4(0.f, 0.f, 0.f, 0.f);
#pragma unroll
        for (int kb = 0; kb < LL; kb += 8) {
            float4 x0 = zp[(size_t)(kb + 0) * D4 + lane];
            float4 x1 = zp[(size_t)(kb + 1) * D4 + lane];
            float4 x2 = zp[(size_t)(kb + 2) * D4 + lane];
            float4 x3 = zp[(size_t)(kb + 3) * D4 + lane];
            float4 x4 = zp[(size_t)(kb + 4) * D4 + lane];
            float4 x5 = zp[(size_t)(kb + 5) * D4 + lane];
            float4 x6 = zp[(size_t)(kb + 6) * D4 + lane];
            float4 x7 = zp[(size_t)(kb + 7) * D4 + lane];
            asm volatile("" ::: "memory");
            a0.x = fmaf(w[kb+0], x0.x, a0.x); a0.y = fmaf(w[kb+0], x0.y, a0.y);
            a0.z = fmaf(w[kb+0], x0.z, a0.z); a0.w = fmaf(w[kb+0], x0.w, a0.w);
            a1.x = fmaf(w[kb+1], x1.x, a1.x); a1.y = fmaf(w[kb+1], x1.y, a1.y);
            a1.z = fmaf(w[kb+1], x1.z, a1.z); a1.w = fmaf(w[kb+1], x1.w, a1.w);
            a0.x = fmaf(w[kb+2], x2.x, a0.x); a0.y = fmaf(w[kb+2], x2.y, a0.y);
            a0.z = fmaf(w[kb+2], x2.z, a0.z); a0.w = fmaf(w[kb+2], x2.w, a0.w);
            a1.x = fmaf(w[kb+3], x3.x, a1.x); a1.y = fmaf(w[kb+3], x3.y, a1.y);
            a1.z = fmaf(w[kb+3], x3.z, a1.z); a1.w = fmaf(w[kb+3], x3.w, a1.w);
            a0.x = fmaf(w[kb+4], x4.x, a0.x); a0.y = fmaf(w[kb+4], x4.y, a0.y);
            a0.z = fmaf(w[kb+4], x4.z, a0.z); a0.w = fmaf(w[kb+4], x4.w, a0.w);
            a1.x = fmaf(w[kb+5], x5.x, a1.x); a1.y = fmaf(w[kb+5], x5.y, a1.y);
            a1.z = fmaf(w[kb+5], x5.z, a1.z); a1.w = fmaf(w[kb+5], x5.w, a1.w);
            a0.x = fmaf(w[kb+6], x6.x, a0.x); a0.y = fmaf(w[kb+6], x6.y, a0.y);
            a0.z = fmaf(w[kb+6], x6.z, a0.z); a0.w = fmaf(w[kb+6], x6.w, a0.w);
            a1.x = fmaf(w[kb+7], x7.x, a1.x); a1.y = fmaf(w[kb+7], x7.y, a1.y);
            a1.z = fmaf(w[kb+7], x7.z, a1.z); a1.w = fmaf(w[kb+7], x7.w, a1.w);
        }
        const int f = b * CC + c;
        ((float4*)g_Bsum)[(size_t)f * D4 + lane] =
            make_float4(a0.x + a1.x, a0.y + a1.y, a0.z + a1.z, a0.w + a1.w);
        if (lane == 0) g_A[f] = r;
    }

    // ---------------- Ticket: last NSCAN blocks run the scan ----------------
    __shared__ int s_scan_id;
    __threadfence();                         // publish Bsum/A before ticket
    if (lane == 0) {
        unsigned old = atomicAdd(&g_ctr, 1u);
        unsigned t = old & (NCHUNK - 1u);    // ticket within this launch
        int id = (int)t - (NCHUNK - NSCAN);  // >=0 for the last NSCAN tickets
        s_scan_id = id;
        if (id >= 0) {
            unsigned target = old - t + NCHUNK;   // all tickets of this launch
            volatile unsigned* p = &g_ctr;
            while ((int)(*p - target) < 0) { }
            __threadfence();
        }
    }
    __syncthreads();
    const int sid = s_scan_id;
    if (sid < 0) return;

    // ---------------- Phase B: scan instance (sb, g) ----------------
    // Pair-combined Hillis-Steele over CC=256 affine maps (verified R7).
    // Composition (A2,B2)∘(A1,B1) = (A2*A1, A2*B1+B2).
    {
        const int sb = sid & (BB - 1);
        const int g  = sid >> 2;             // d4 lane 0..127
        const int i  = lane;                 // pair id 0..127
        const int f0 = sb * CC + 2 * i;
        const int f1 = f0 + 1;

        float a0 = g_A[f0];
        float a1 = g_A[f1];
        float4 v0 = ((const float4*)g_Bsum)[(size_t)f0 * D4 + g];
        float4 v1 = ((const float4*)g_Bsum)[(size_t)f1 * D4 + g];

        float  ac = a1 * a0;
        float4 bc = make_float4(fmaf(a1, v0.x, v1.x), fmaf(a1, v0.y, v1.y),
                                fmaf(a1, v0.z, v1.z), fmaf(a1, v0.w, v1.w));

        __shared__ float sA[128];
        __shared__ float4 sB[128];
        sA[i] = ac; sB[i] = bc;
        __syncthreads();
#pragma unroll
        for (int s = 1; s < 128; s <<= 1) {
            float pa = 1.0f;
            float4 pb = make_float4(0.f, 0.f, 0.f, 0.f);
            if (i >= s) { pa = sA[i - s]; pb = sB[i - s]; }
            __syncthreads();
            if (i >= s) {
                bc.x = fmaf(ac, pb.x, bc.x);
                bc.y = fmaf(ac, pb.y, bc.y);
                bc.z = fmaf(ac, pb.z, bc.z);
                bc.w = fmaf(ac, pb.w, bc.w);
                ac *= pa;
                sA[i] = ac; sB[i] = bc;
            }
            __syncthreads();
        }
        float4 Eb = (i == 0) ? make_float4(0.f, 0.f, 0.f, 0.f) : sB[i - 1];
        float4* __restrict__ zi = (float4*)g_Zinit;
        zi[(size_t)f0 * D4 + g] = Eb;
        zi[(size_t)f1 * D4 + g] =
            make_float4(fmaf(a0, Eb.x, v0.x), fmaf(a0, Eb.y, v0.y),
                        fmaf(a0, Eb.z, v0.z), fmaf(a0, Eb.w, v0.w));
    }
}

// ---------------------------------------------------------------------------
// kB = K3 VERBATIM from the 17.15us R5 kernel (no launch-bounds reg cap, no
// compiler barrier): per-chunk local scan seeded with Zinit; mask; write out.
// Masked chunks zero-fill with no loads.
// ---------------------------------------------------------------------------
__global__ void __launch_bounds__(128) kB_scan_out(
    const float* __restrict__ z, const float* __restrict__ P,
    const int* __restrict__ lengths, float* __restrict__ out)
{
    const int b = blockIdx.x;
    const int c = blockIdx.y;
    const int lane = threadIdx.x;
    const int len = lengths[b];
    const int t0 = c * LL;

    float4* __restrict__ op = (float4*)(out + ((size_t)b * TT + t0) * DD);

    if (t0 >= len) {
        float4 zero = make_float4(0.f, 0.f, 0.f, 0.f);
#pragma unroll
        for (int k = 0; k < LL; ++k) op[(size_t)k * D4 + lane] = zero;
        return;
    }

    __shared__ float sp[LL], sq[LL];

    // carry load issued early, latency hidden behind P/smem setup
    float4 zv = ((const float4*)g_Zinit)[(size_t)(b * CC + c) * D4 + lane];

    if (lane < LL) {
        float p = P[b * TT + t0 + lane];
        p = fminf(fmaxf(p, 0.0f), 1.0f - 1e-6f);
        sq[lane] = 1.0f - p;
        sp[lane] = fmaxf(p, 1e-6f);
    }
    __syncthreads();

    const float4* __restrict__ zp =
        (const float4*)(z + ((size_t)b * TT + t0) * DD);

#pragma unroll
    for (int kb = 0; kb < LL; kb += 8) {
        float4 x0 = zp[(size_t)(kb + 0) * D4 + lane];
        float4 x1 = zp[(size_t)(kb + 1) * D4 + lane];
        float4 x2 = zp[(size_t)(kb + 2) * D4 + lane];
        float4 x3 = zp[(size_t)(kb + 3) * D4 + lane];
        float4 x4 = zp[(size_t)(kb + 4) * D4 + lane];
        float4 x5 = zp[(size_t)(kb + 5) * D4 + lane];
        float4 x6 = zp[(size_t)(kb + 6) * D4 + lane];
        float4 x7 = zp[(size_t)(kb + 7) * D4 + lane];
#pragma unroll
        for (int j = 0; j < 8; ++j) {
            const int kk = kb + j;
            float4 x = (j == 0) ? x0 : (j == 1) ? x1 : (j == 2) ? x2 : (j == 3) ? x3
                     : (j == 4) ? x4 : (j == 5) ? x5 : (j == 6) ? x6 : x7;
            float q = sq[kk], p = sp[kk];
            zv.x = fmaf(q, zv.x, p * x.x);
            zv.y = fmaf(q, zv.y, p * x.y);
            zv.z = fmaf(q, zv.z, p * x.z);
            zv.w = fmaf(q, zv.w, p * x.w);
            float m = (t0 + kk < len) ? 1.0f : 0.0f;
            op[(size_t)kk * D4 + lane] =
                make_float4(zv.x * m, zv.y * m, zv.z * m, zv.w * m);
        }
    }
}

extern "C" void kernel_launch(void* const* d_in, const int* in_sizes, int n_in,
                              void* d_out, int out_size)
{
    const float* z = (const float*)d_in[0];
    const float* P = (const float*)d_in[1];
    const int* lengths = (const int*)d_in[2];
    float* out = (float*)d_out;

    dim3 grid(BB, CC);         // b fastest -> masked/active mixed across SMs
    kA_summary_scan<<<grid, 128>>>(z, P, lengths);
    kB_scan_out<<<grid, 128>>>(z, P, lengths, out);
}